// round 14
// baseline (speedup 1.0000x reference)
#include <cuda_runtime.h>
#include <cuda_bf16.h>

#define EPSF 1e-9f
#define WPB  16              // warps per block (512 threads)
#define TARGET_WARPS 7104    // 148 SMs * 3 blocks * 16 warps
#define MAX_STAGE 352        // max staged bodies per block (2*len)

#define FIX_SCALE   4294967296.0f              // 2^32
#define FIX_INV     2.3283064365386963e-10f    // 2^-32

// fixed-point accumulators per body: [F][0]=x, [F][1]=y  (zero-init, reset by finalize)
__device__ unsigned long long g_acc[16384][2];
__device__ unsigned g_cnt = 0;

__global__ __launch_bounds__(512, 3)
void pairs_kernel(const float2* __restrict__ cpos,
                  const float*  __restrict__ crad,
                  const float2* __restrict__ apos,
                  const float2* __restrict__ ahalf,
                  float2* __restrict__ out,
                  int nc, int na, int gc, int groups, int C, int len)
{
    __shared__ float4 s_body[MAX_STAGE];
    __shared__ int s_last;

    const int lane = threadIdx.x & 31;
    const int warp = threadIdx.x >> 5;
    const int unit = blockIdx.x * WPB + warp;
    const int L = nc + na;

    // ---- block-level staging: chunk range shared by all warps of this block ----
    const int u0 = blockIdx.x * WPB;
    const int c0 = u0 / groups;
    const int lo_blk = c0 * len;
    const int hi_blk = min(L, lo_blk + 2 * len);

    for (int t = lo_blk + threadIdx.x; t < hi_blk; t += 512) {
        float4 v;
        if (t < nc) {
            float2 p = cpos[t];
            v = make_float4(p.x, p.y, 0.5f * crad[t], 0.0f);
        } else {
            float2 p = apos[t - nc];
            float2 h = ahalf[t - nc];
            v = make_float4(p.x, p.y, h.x, h.y);
        }
        s_body[t - lo_blk] = v;
    }
    __syncthreads();

    // ================= phase 1: pair partial sums =================
    if (unit < groups * C) {
        const int c = unit / groups;
        const int g = unit - c * groups;
        const int lo = c * len;
        const int hi = min(L, lo + len);
        const float4* __restrict__ sb = s_body - lo_blk;   // index by flattened t

        float ax = 0.0f, ay = 0.0f;
        int  F = -1;                 // accumulator slot (-1 = invalid lane)

        if (g < gc) {
            // ------------- circle body -------------
            int i  = g * 32 + lane;
            int ii = min(i, nc - 1);
            if (i < nc) F = i;
            const float2 pp = cpos[ii];
            const float rih = 0.5f * crad[ii];
            const float px = pp.x, py = pp.y;

            // circle vs circle: t in [lo, min(hi,nc))
            int e1 = min(hi, nc);
            #pragma unroll 8
            for (int t = lo; t < e1; ++t) {
                float4 q = sb[t];
                float dx = px - q.x, dy = py - q.y;
                float d2 = fmaf(dx, dx, dy * dy);
                float rsh = rih + q.z;
                float inv = rsqrtf(d2);                    // inf at d2=0; gated below
                float f = fmaxf(fmaf(rsh, inv, -0.5f), 0.0f);
                f = (d2 > EPSF) ? f : 0.0f;
                ax = fmaf(f, dx, ax);
                ay = fmaf(f, dy, ay);
            }

            // circle vs aabb: t in [max(lo,nc), hi)
            int s2 = max(lo, nc);
            #pragma unroll 4
            for (int t = s2; t < hi; ++t) {
                float4 q = sb[t];
                float rx = px - q.x, ry = py - q.y;
                float mx = fmaxf(fabsf(rx) - q.z, 0.0f);
                float my = fmaxf(fabsf(ry) - q.w, 0.0f);
                float d2 = fmaf(mx, mx, my * my);
                float inv = rsqrtf(d2);
                float f = fmaxf(fmaf(rih, inv, -0.5f), 0.0f);
                f = (d2 > EPSF) ? f : 0.0f;
                ax = fmaf(f, copysignf(mx, rx), ax);
                ay = fmaf(f, copysignf(my, ry), ay);
            }
        } else {
            // ------------- aabb body -------------
            int b  = (g - gc) * 32 + lane;
            int bb = min(b, na - 1);
            if (b < na) F = gc * 32 + b;
            const float2 pp = apos[bb];
            const float2 hh = ahalf[bb];
            const float px = pp.x, py = pp.y;
            const float hx = hh.x, hy = hh.y;
            const int self_t = nc + bb;

            // circle pushes on box (equal-and-opposite): t in [lo, min(hi,nc))
            int e1 = min(hi, nc);
            #pragma unroll 4
            for (int t = lo; t < e1; ++t) {
                float4 q = sb[t];
                float rx = q.x - px, ry = q.y - py;
                float mx = fmaxf(fabsf(rx) - hx, 0.0f);
                float my = fmaxf(fabsf(ry) - hy, 0.0f);
                float d2 = fmaf(mx, mx, my * my);
                float inv = rsqrtf(d2);
                float f = fmaxf(fmaf(q.z, inv, -0.5f), 0.0f);
                f = (d2 > EPSF) ? f : 0.0f;
                ax = fmaf(-f, copysignf(mx, rx), ax);
                ay = fmaf(-f, copysignf(my, ry), ay);
            }

            // aabb vs aabb: t in [max(lo,nc), hi)
            int s2 = max(lo, nc);
            #pragma unroll 4
            for (int t = s2; t < hi; ++t) {
                float4 q = sb[t];
                float dax = px - q.x, day = py - q.y;
                float ovx = (hx + q.z) - fabsf(dax);
                float ovy = (hy + q.w) - fabsf(day);
                bool hit  = (t != self_t) & (ovx > 0.0f) & (ovy > 0.0f);
                bool usex = (ovx <= ovy);
                float pxs = copysignf(0.5f * ovx, dax);
                float pys = copysignf(0.5f * ovy, day);
                ax += (hit & usex)  ? pxs : 0.0f;
                ay += (hit & !usex) ? pys : 0.0f;
            }
        }

        // Q32.32 fixed-point accumulation (associative -> deterministic)
        if (F >= 0) {
            long long vx = (long long)(ax * FIX_SCALE);
            long long vy = (long long)(ay * FIX_SCALE);
            atomicAdd(&g_acc[F][0], (unsigned long long)vx);
            atomicAdd(&g_acc[F][1], (unsigned long long)vy);
        }
    }

    // ================= arrival ticket =================
    __threadfence();            // make this thread's atomics globally visible
    __syncthreads();
    if (threadIdx.x == 0) {
        unsigned t = atomicAdd(&g_cnt, 1u);
        s_last = (t == gridDim.x - 1) ? 1 : 0;
    }
    __syncthreads();

    // ================= finalize: last-arriving block only =================
    if (s_last) {
        __threadfence();
        int tot = nc + na;
        for (int b = threadIdx.x; b < tot; b += 512) {
            int F = (b < nc) ? b : gc * 32 + (b - nc);
            // read-and-reset (L2 atomic; leaves zero for next launch)
            unsigned long long ux = atomicExch(&g_acc[F][0], 0ULL);
            unsigned long long uy = atomicExch(&g_acc[F][1], 0ULL);
            float sx = (float)((long long)ux) * FIX_INV;
            float sy = (float)((long long)uy) * FIX_INV;
            float2 base = (b < nc) ? cpos[b] : apos[b - nc];
            out[b] = make_float2(base.x + sx, base.y + sy);
        }
        __syncthreads();
        if (threadIdx.x == 0) g_cnt = 0;     // reset ticket for next launch
    }
}

extern "C" void kernel_launch(void* const* d_in, const int* in_sizes, int n_in,
                              void* d_out, int out_size)
{
    const float2* cpos  = (const float2*)d_in[0];
    const float*  crad  = (const float*)d_in[1];
    const float2* apos  = (const float2*)d_in[2];
    const float2* ahalf = (const float2*)d_in[3];
    float2* out = (float2*)d_out;

    int nc = in_sizes[1];        // circle_radius element count
    int na = in_sizes[2] / 2;    // aabb_pos has na*2 elements

    int gc = (nc + 31) / 32;
    int ga = (na + 31) / 32;
    int groups = gc + ga;
    int L = nc + na;

    int C = TARGET_WARPS / groups;            // 192 groups -> 37
    if (C < 1) C = 1;
    // chunk length must fit the shared staging buffer (2*len <= MAX_STAGE)
    int minC = (L + (MAX_STAGE / 2 - 1)) / (MAX_STAGE / 2);
    if (C < minC) C = minC;
    // accumulator table bound: gc*32 + na must fit (16384); C has no table impact now,
    // but keep unit count sane
    if (groups * C > 16384) C = 16384 / groups;

    int len = (L + C - 1) / C;

    int units = groups * C;
    int grid1 = (units + WPB - 1) / WPB;      // 444 nominal

    pairs_kernel<<<grid1, 512>>>(cpos, crad, apos, ahalf, out,
                                 nc, na, gc, groups, C, len);
}